// round 5
// baseline (speedup 1.0000x reference)
#include <cuda_runtime.h>
#include <cuda_fp16.h>
#include <cstdint>

// ====================== tile/pipeline constants ======================
#define STG      22528            // per-stage smem: A 8192 (128x64B) + B 14336 (224x64B)
#define STAGES   4
#define SMEM_DYN (STAGES * STG + 128)

// ====================== device scratch ======================
__device__ __align__(16) __half g_x[(size_t)32 * 58 * 58 * 256];  // padded NHWC fp16 (k-permuted)
__device__ __align__(16) __half g_w[(size_t)9 * 256 * 256];       // [tap][co][ci] = +-1 (k-permuted)

// ====================== helpers ======================
__device__ __forceinline__ uint32_t smem_u32(const void* p) {
    uint32_t a;
    asm("{ .reg .u64 t; cvta.to.shared.u64 t, %1; cvt.u32.u64 %0, t; }" : "=r"(a) : "l"(p));
    return a;
}

// within-16 k permutation: k -> pos so that (2t,2t+1) and (2t+8,2t+9) are the
// two halves of one 8-byte lds.64 for fragment lane t.
__device__ __forceinline__ int permci(int ci) {
    int j = ci & 15;
    return (ci & ~15) | (((j >> 1) & 3) << 2) | ((j >> 3) << 1) | (j & 1);
}

__device__ __forceinline__ void cp16(uint32_t d, const void* s) {
    asm volatile("cp.async.cg.shared.global [%0], [%1], 16;" :: "r"(d), "l"(s) : "memory");
}
__device__ __forceinline__ void ld64(uint32_t& x, uint32_t& y, uint32_t a) {
    asm volatile("ld.shared.v2.u32 {%0,%1}, [%2];" : "=r"(x), "=r"(y) : "r"(a));
}
__device__ __forceinline__ void mma16816(float* c, uint32_t a0, uint32_t a1, uint32_t a2,
                                         uint32_t a3, uint32_t b0, uint32_t b1) {
    asm volatile(
        "mma.sync.aligned.m16n8k16.row.col.f32.f16.f16.f32 "
        "{%0,%1,%2,%3}, {%4,%5,%6,%7}, {%8,%9}, {%0,%1,%2,%3};"
        : "+f"(c[0]), "+f"(c[1]), "+f"(c[2]), "+f"(c[3])
        : "r"(a0), "r"(a1), "r"(a2), "r"(a3), "r"(b0), "r"(b1));
}

// ====================== prep kernels ======================
__global__ void zero_x_kernel() {
    size_t i = (size_t)blockIdx.x * 256 + threadIdx.x;   // 3,444,736 float4 exactly
    reinterpret_cast<float4*>(g_x)[i] = make_float4(0.f, 0.f, 0.f, 0.f);
}

// x NCHW f32 -> g_x padded NHWC fp16 with k-permutation. grid 32*56*2, 256 thr.
__global__ void prep_x_kernel(const float* __restrict__ x) {
    __shared__ float tile[128][57];
    const int b  = blockIdx.x;
    const int ch = b & 1;
    const int h  = (b >> 1) % 56;
    const int n  = (b >> 1) / 56;
    const float* src = x + (size_t)(n * 256 + ch * 128) * 3136 + h * 56;
    for (int i = threadIdx.x; i < 128 * 56; i += 256) {
        int ci = i / 56, w = i - 56 * ci;
        tile[ci][w] = src[(size_t)ci * 3136 + w];
    }
    __syncthreads();
    __half* dst = g_x + (size_t)n * 861184 + ((h + 1) * 58 + 1) * 256;
    for (int j = threadIdx.x; j < 64 * 56; j += 256) {
        int w  = j >> 6, cp = j & 63;
        int ci = ch * 128 + 2 * cp;                       // even -> permuted pair adjacent
        __half2 v = __floats2half2_rn(tile[2 * cp][w], tile[2 * cp + 1][w]);
        *reinterpret_cast<__half2*>(dst + (size_t)w * 256 + permci(ci)) = v;
    }
}

// weight [co][ci][3][3] f32 -> g_w[tap][co][perm(ci)] = +-1 fp16. grid 2304, 256 thr.
__global__ void prep_w_kernel(const float* __restrict__ w) {
    int idx = blockIdx.x * 256 + threadIdx.x;             // co*2304 + ci*9 + tap
    int co  = idx / 2304;
    int r   = idx - co * 2304;
    int ci  = r / 9;
    int tap = r - ci * 9;
    g_w[(size_t)(tap * 256 + co) * 256 + permci(ci)] = __float2half(w[idx] >= 0.f ? 1.f : -1.f);
}

// ====================== main kernel ======================
// grid 896 = 2 cout-halves * 14 row-quads * 32 images; 256 threads (8 warps 2x4).
// Warp tile 64x56: 4 m16-frags x 7 n8-frags, K=16 per mma, 2 ksteps per 32-ci stage.
__global__ void __launch_bounds__(256, 1)
bconv_main_kernel(const float* __restrict__ bias, float* __restrict__ out) {
    extern __shared__ char dsm[];
    const uint32_t base = (smem_u32(dsm) + 127u) & ~127u;

    const int tid  = threadIdx.x;
    const int lane = tid & 31;
    const int wid  = tid >> 5;
    const int g    = lane >> 2;
    const int t    = lane & 3;
    const int wm   = wid >> 2;     // 0..1  (m warp row)
    const int wn   = wid & 3;      // 0..3  (n warp col = output h row)

    const int bid   = blockIdx.x;
    const int mb    = bid & 1;
    const int ntile = (bid >> 1) % 14;
    const int n     = bid / 28;
    const int h0    = ntile * 4;

    const __half* xn = g_x + (size_t)n * 861184;

    // ---- per-thread cp.async chunk tables (16B chunks) ----
    uint32_t aD[2], aG[2], bD[4], bG[4];
#pragma unroll
    for (int i = 0; i < 2; i++) {
        int c   = tid + 256 * i;          // A chunk 0..511
        int row = c >> 2, cb = c & 3;
        aD[i] = (uint32_t)(row * 64 + ((cb ^ (row & 3)) << 4));
        aG[i] = (uint32_t)((mb * 128 + row) * 256 + cb * 8);
    }
#pragma unroll
    for (int i = 0; i < 4; i++) {
        int c    = tid + 256 * i;         // B chunk 0..895 (i==3 valid only for tid<128)
        int prow = c >> 2, cb = c & 3;
        int pr   = prow / 56, pw = prow - 56 * pr;
        bD[i] = (uint32_t)(8192 + prow * 64 + ((cb ^ (prow & 3)) << 4));
        bG[i] = (uint32_t)(((h0 + pr) * 58 + pw) * 256 + cb * 8);
    }

    auto load_stage = [&](int s, uint32_t sb) {
        int tap = s >> 3, kc = s & 7;
        int dh  = tap / 3, dw = tap - 3 * dh;
        uint32_t ad = (uint32_t)(tap * 65536 + kc * 32);
        uint32_t bd = (uint32_t)((dh * 58 + dw) * 256 + kc * 32);
        cp16(sb + aD[0], g_w + aG[0] + ad);
        cp16(sb + aD[1], g_w + aG[1] + ad);
        cp16(sb + bD[0], xn + bG[0] + bd);
        cp16(sb + bD[1], xn + bG[1] + bd);
        cp16(sb + bD[2], xn + bG[2] + bd);
        if (tid < 128) cp16(sb + bD[3], xn + bG[3] + bd);
        asm volatile("cp.async.commit_group;" ::: "memory");
    };

    // ---- LDS fragment address offsets (relative to stage base; ^32 selects kstep) ----
    uint32_t rA[4][2], rB[7];
#pragma unroll
    for (int mi = 0; mi < 4; mi++)
#pragma unroll
        for (int hh = 0; hh < 2; hh++) {
            int row = wm * 64 + mi * 16 + g + 8 * hh;
            rA[mi][hh] = (uint32_t)(row * 64 + (((t >> 1) ^ (row & 3)) << 4) + 8 * (t & 1));
        }
#pragma unroll
    for (int ni = 0; ni < 7; ni++) {
        int prow = wn * 56 + ni * 8 + g;
        rB[ni] = (uint32_t)(8192 + prow * 64 + (((t >> 1) ^ (prow & 3)) << 4) + 8 * (t & 1));
    }

    float acc[4][7][4];
#pragma unroll
    for (int mi = 0; mi < 4; mi++)
#pragma unroll
        for (int ni = 0; ni < 7; ni++)
#pragma unroll
            for (int k = 0; k < 4; k++) acc[mi][ni][k] = 0.f;

    // ---- prologue: stages 0..2 ----
    for (int s = 0; s < 3; s++) load_stage(s, base + s * STG);
    asm volatile("cp.async.wait_group 2;" ::: "memory");
    __syncthreads();

    // ---- mainloop: 72 stages ----
    for (int s = 0; s < 72; s++) {
        if (s + 3 < 72) load_stage(s + 3, base + ((s + 3) & 3) * STG);
        else asm volatile("cp.async.commit_group;" ::: "memory");

        const uint32_t sb = base + (s & 3) * STG;
#pragma unroll
        for (int ks = 0; ks < 2; ks++) {
            const uint32_t xr = (uint32_t)(ks << 5);
            uint32_t a0[4], a1[4], a2[4], a3[4];
#pragma unroll
            for (int mi = 0; mi < 4; mi++) {
                ld64(a0[mi], a2[mi], sb + (rA[mi][0] ^ xr));
                ld64(a1[mi], a3[mi], sb + (rA[mi][1] ^ xr));
            }
#pragma unroll
            for (int ni = 0; ni < 7; ni++) {
                uint32_t b0, b1;
                ld64(b0, b1, sb + (rB[ni] ^ xr));
#pragma unroll
                for (int mi = 0; mi < 4; mi++)
                    mma16816(acc[mi][ni], a0[mi], a1[mi], a2[mi], a3[mi], b0, b1);
            }
        }
        asm volatile("cp.async.wait_group 2;" ::: "memory");
        __syncthreads();
    }

    // ---- epilogue: registers -> gmem (float2), + binarized bias ----
    const int h = h0 + wn;
#pragma unroll
    for (int mi = 0; mi < 4; mi++) {
        int mlo = mb * 128 + wm * 64 + mi * 16 + g;
        float blo = (bias[mlo]     >= 0.f) ? 1.f : -1.f;
        float bhi = (bias[mlo + 8] >= 0.f) ? 1.f : -1.f;
        size_t olo = ((size_t)(n * 256 + mlo)) * 3136 + h * 56;
        size_t ohi = olo + (size_t)8 * 3136;
#pragma unroll
        for (int ni = 0; ni < 7; ni++) {
            int w = ni * 8 + 2 * t;
            float2 v0 = make_float2(acc[mi][ni][0] + blo, acc[mi][ni][1] + blo);
            float2 v1 = make_float2(acc[mi][ni][2] + bhi, acc[mi][ni][3] + bhi);
            *reinterpret_cast<float2*>(out + olo + w) = v0;
            *reinterpret_cast<float2*>(out + ohi + w) = v1;
        }
    }
}

// ====================== launch ======================
extern "C" void kernel_launch(void* const* d_in, const int* in_sizes, int n_in,
                              void* d_out, int out_size) {
    const float* x    = (const float*)d_in[0];
    const float* w    = (const float*)d_in[1];
    const float* bias = (const float*)d_in[2];
    float* out        = (float*)d_out;

    cudaFuncSetAttribute(bconv_main_kernel,
                         cudaFuncAttributeMaxDynamicSharedMemorySize, SMEM_DYN);

    zero_x_kernel<<<13456, 256>>>();
    prep_x_kernel<<<32 * 56 * 2, 256>>>(x);
    prep_w_kernel<<<2304, 256>>>(w);
    bconv_main_kernel<<<896, 256, SMEM_DYN>>>(bias, out);
}

// round 6
// speedup vs baseline: 1.0940x; 1.0940x over previous
#include <cuda_runtime.h>
#include <cuda_fp16.h>
#include <cstdint>

// ====================== tile/pipeline constants ======================
// CTA: 128 threads (4 warps 2x2), tile 128 couts x 112 pixels (2 output rows)
#define STG      15360            // per-stage smem: A 8192 (128x64B) + B 7168 (112x64B)
#define STAGES   4
#define SMEM_DYN (STAGES * STG + 128)

// ====================== device scratch ======================
__device__ __align__(16) __half g_x[(size_t)32 * 58 * 58 * 256];  // padded NHWC fp16 (k-permuted)
__device__ __align__(16) __half g_w[(size_t)9 * 256 * 256];       // [tap][co][ci] = +-1 (k-permuted)

// ====================== helpers ======================
__device__ __forceinline__ uint32_t smem_u32(const void* p) {
    uint32_t a;
    asm("{ .reg .u64 t; cvta.to.shared.u64 t, %1; cvt.u32.u64 %0, t; }" : "=r"(a) : "l"(p));
    return a;
}

// within-16 k permutation so each lane's mma fragment pair is one lds.64
__device__ __forceinline__ int permci(int ci) {
    int j = ci & 15;
    return (ci & ~15) | (((j >> 1) & 3) << 2) | ((j >> 3) << 1) | (j & 1);
}

__device__ __forceinline__ void cp16(uint32_t d, const void* s) {
    asm volatile("cp.async.cg.shared.global [%0], [%1], 16;" :: "r"(d), "l"(s) : "memory");
}
__device__ __forceinline__ void ld64(uint32_t& x, uint32_t& y, uint32_t a) {
    asm volatile("ld.shared.v2.u32 {%0,%1}, [%2];" : "=r"(x), "=r"(y) : "r"(a));
}
__device__ __forceinline__ void mma16816(float* c, uint32_t a0, uint32_t a1, uint32_t a2,
                                         uint32_t a3, uint32_t b0, uint32_t b1) {
    asm volatile(
        "mma.sync.aligned.m16n8k16.row.col.f32.f16.f16.f32 "
        "{%0,%1,%2,%3}, {%4,%5,%6,%7}, {%8,%9}, {%0,%1,%2,%3};"
        : "+f"(c[0]), "+f"(c[1]), "+f"(c[2]), "+f"(c[3])
        : "r"(a0), "r"(a1), "r"(a2), "r"(a3), "r"(b0), "r"(b1));
}

// ====================== prep kernels ======================
// zero only the pad border (h in {0,57} full width; w in {0,57} for h=1..56)
__global__ void zero_border_kernel() {
    const int n = blockIdx.x;                       // 32 images
    __half* xb = g_x + (size_t)n * 861184;
    for (int c = threadIdx.x; c < 7296; c += 256) { // 228 border px * 32 uint4
        int px = c >> 5, q = c & 31;
        int h, w;
        if (px < 58)       { h = 0;        w = px; }
        else if (px < 116) { h = 57;       w = px - 58; }
        else if (px < 172) { h = px - 115; w = 0; }
        else               { h = px - 171; w = 57; }
        reinterpret_cast<uint4*>(xb + ((size_t)h * 58 + w) * 256)[q] =
            make_uint4(0u, 0u, 0u, 0u);
    }
}

// x NCHW f32 -> g_x padded NHWC fp16 with k-permutation. grid 32*56*2, 256 thr.
__global__ void prep_x_kernel(const float* __restrict__ x) {
    __shared__ float tile[128][57];
    const int b  = blockIdx.x;
    const int ch = b & 1;
    const int h  = (b >> 1) % 56;
    const int n  = (b >> 1) / 56;
    const float* src = x + (size_t)(n * 256 + ch * 128) * 3136 + h * 56;
    for (int i = threadIdx.x; i < 128 * 56; i += 256) {
        int ci = i / 56, w = i - 56 * ci;
        tile[ci][w] = src[(size_t)ci * 3136 + w];
    }
    __syncthreads();
    __half* dst = g_x + (size_t)n * 861184 + ((h + 1) * 58 + 1) * 256;
    for (int j = threadIdx.x; j < 64 * 56; j += 256) {
        int w  = j >> 6, cp = j & 63;
        int ci = ch * 128 + 2 * cp;
        __half2 v = __floats2half2_rn(tile[2 * cp][w], tile[2 * cp + 1][w]);
        *reinterpret_cast<__half2*>(dst + (size_t)w * 256 + permci(ci)) = v;
    }
}

// weight [co][ci][3][3] f32 -> g_w[tap][co][perm(ci)] = +-1 fp16. grid 2304, 256 thr.
__global__ void prep_w_kernel(const float* __restrict__ w) {
    int idx = blockIdx.x * 256 + threadIdx.x;             // co*2304 + ci*9 + tap
    int co  = idx / 2304;
    int r   = idx - co * 2304;
    int ci  = r / 9;
    int tap = r - ci * 9;
    g_w[(size_t)(tap * 256 + co) * 256 + permci(ci)] = __float2half(w[idx] >= 0.f ? 1.f : -1.f);
}

// ====================== main kernel ======================
// grid 1792 = 2 cout-halves * 28 row-pairs * 32 images; 128 threads (4 warps 2x2).
// Warp tile 64x56: 4 m16-frags x 7 n8-frags, 2 ksteps per 32-ci stage.
__global__ void __launch_bounds__(128)
bconv_main_kernel(const float* __restrict__ bias, float* __restrict__ out) {
    extern __shared__ char dsm[];
    const uint32_t base = (smem_u32(dsm) + 127u) & ~127u;

    const int tid  = threadIdx.x;
    const int lane = tid & 31;
    const int wid  = tid >> 5;
    const int g    = lane >> 2;
    const int t    = lane & 3;
    const int wm   = wid >> 1;     // 0..1  (m warp half)
    const int wn   = wid & 1;      // 0..1  (output row within pair)

    const int bid   = blockIdx.x;
    const int mb    = bid & 1;
    const int rp    = (bid >> 1) % 28;
    const int n     = bid / 56;
    const int h0    = rp * 2;

    const __half* xn = g_x + (size_t)n * 861184;

    // ---- per-thread cp.async chunk tables (16B chunks) ----
    uint32_t aD[4], aG[4], bD[4], bG[4];
#pragma unroll
    for (int i = 0; i < 4; i++) {
        int c   = tid + 128 * i;          // A chunk 0..511
        int row = c >> 2, cb = c & 3;
        aD[i] = (uint32_t)(row * 64 + ((cb ^ (row & 3)) << 4));
        aG[i] = (uint32_t)((mb * 128 + row) * 256 + cb * 8);
    }
#pragma unroll
    for (int i = 0; i < 4; i++) {
        int c    = (i < 3) ? (tid + 128 * i) : (384 + tid);   // B chunk 0..447 (i==3: tid<64)
        int prow = c >> 2, cb = c & 3;
        int pr   = prow / 56, pw = prow - 56 * pr;
        bD[i] = (uint32_t)(8192 + prow * 64 + ((cb ^ (prow & 3)) << 4));
        bG[i] = (uint32_t)(((h0 + pr) * 58 + pw) * 256 + cb * 8);
    }

    auto load_stage = [&](int s, uint32_t sb) {
        int tap = s >> 3, kc = s & 7;
        int dh  = tap / 3, dw = tap - 3 * dh;
        uint32_t ad = (uint32_t)(tap * 65536 + kc * 32);
        uint32_t bd = (uint32_t)((dh * 58 + dw) * 256 + kc * 32);
        cp16(sb + aD[0], g_w + aG[0] + ad);
        cp16(sb + aD[1], g_w + aG[1] + ad);
        cp16(sb + aD[2], g_w + aG[2] + ad);
        cp16(sb + aD[3], g_w + aG[3] + ad);
        cp16(sb + bD[0], xn + bG[0] + bd);
        cp16(sb + bD[1], xn + bG[1] + bd);
        cp16(sb + bD[2], xn + bG[2] + bd);
        if (tid < 64) cp16(sb + bD[3], xn + bG[3] + bd);
        asm volatile("cp.async.commit_group;" ::: "memory");
    };

    // ---- LDS fragment address offsets (relative to stage base; ^32 selects kstep) ----
    uint32_t rA[4][2], rB[7];
#pragma unroll
    for (int mi = 0; mi < 4; mi++)
#pragma unroll
        for (int hh = 0; hh < 2; hh++) {
            int row = wm * 64 + mi * 16 + g + 8 * hh;
            rA[mi][hh] = (uint32_t)(row * 64 + (((t >> 1) ^ (row & 3)) << 4) + 8 * (t & 1));
        }
#pragma unroll
    for (int ni = 0; ni < 7; ni++) {
        int prow = wn * 56 + ni * 8 + g;
        rB[ni] = (uint32_t)(8192 + prow * 64 + (((t >> 1) ^ (prow & 3)) << 4) + 8 * (t & 1));
    }

    float acc[4][7][4];
#pragma unroll
    for (int mi = 0; mi < 4; mi++)
#pragma unroll
        for (int ni = 0; ni < 7; ni++)
#pragma unroll
            for (int k = 0; k < 4; k++) acc[mi][ni][k] = 0.f;

    // ---- prologue: stages 0..2 ----
    for (int s = 0; s < 3; s++) load_stage(s, base + s * STG);
    asm volatile("cp.async.wait_group 2;" ::: "memory");
    __syncthreads();

    // ---- mainloop: 72 stages ----
    for (int s = 0; s < 72; s++) {
        if (s + 3 < 72) load_stage(s + 3, base + ((s + 3) & 3) * STG);
        else asm volatile("cp.async.commit_group;" ::: "memory");

        const uint32_t sb = base + (s & 3) * STG;
#pragma unroll
        for (int ks = 0; ks < 2; ks++) {
            const uint32_t xr = (uint32_t)(ks << 5);
            uint32_t a0[4], a1[4], a2[4], a3[4];
#pragma unroll
            for (int mi = 0; mi < 4; mi++) {
                ld64(a0[mi], a2[mi], sb + (rA[mi][0] ^ xr));
                ld64(a1[mi], a3[mi], sb + (rA[mi][1] ^ xr));
            }
#pragma unroll
            for (int ni = 0; ni < 7; ni++) {
                uint32_t b0, b1;
                ld64(b0, b1, sb + (rB[ni] ^ xr));
#pragma unroll
                for (int mi = 0; mi < 4; mi++)
                    mma16816(acc[mi][ni], a0[mi], a1[mi], a2[mi], a3[mi], b0, b1);
            }
        }
        asm volatile("cp.async.wait_group 2;" ::: "memory");
        __syncthreads();
    }

    // ---- epilogue: registers -> gmem (float2), + binarized bias ----
    const int h = h0 + wn;
#pragma unroll
    for (int mi = 0; mi < 4; mi++) {
        int mlo = mb * 128 + wm * 64 + mi * 16 + g;
        float blo = (bias[mlo]     >= 0.f) ? 1.f : -1.f;
        float bhi = (bias[mlo + 8] >= 0.f) ? 1.f : -1.f;
        size_t olo = ((size_t)(n * 256 + mlo)) * 3136 + h * 56;
        size_t ohi = olo + (size_t)8 * 3136;
#pragma unroll
        for (int ni = 0; ni < 7; ni++) {
            int w = ni * 8 + 2 * t;
            float2 v0 = make_float2(acc[mi][ni][0] + blo, acc[mi][ni][1] + blo);
            float2 v1 = make_float2(acc[mi][ni][2] + bhi, acc[mi][ni][3] + bhi);
            *reinterpret_cast<float2*>(out + olo + w) = v0;
            *reinterpret_cast<float2*>(out + ohi + w) = v1;
        }
    }
}

// ====================== launch ======================
extern "C" void kernel_launch(void* const* d_in, const int* in_sizes, int n_in,
                              void* d_out, int out_size) {
    const float* x    = (const float*)d_in[0];
    const float* w    = (const float*)d_in[1];
    const float* bias = (const float*)d_in[2];
    float* out        = (float*)d_out;

    cudaFuncSetAttribute(bconv_main_kernel,
                         cudaFuncAttributeMaxDynamicSharedMemorySize, SMEM_DYN);

    zero_border_kernel<<<32, 256>>>();
    prep_x_kernel<<<32 * 56 * 2, 256>>>(x);
    prep_w_kernel<<<2304, 256>>>(w);
    bconv_main_kernel<<<1792, 128, SMEM_DYN>>>(bias, out);
}

// round 8
// speedup vs baseline: 1.1889x; 1.0868x over previous
#include <cuda_runtime.h>
#include <cuda_fp16.h>
#include <cstdint>

// ====================== tile/pipeline constants ======================
// CTA: 128 threads (4 warps 2x2), tile 128 couts x 112 pixels (2 output rows)
#define STG      15360            // per-stage smem: A 8192 (128x64B) + B 7168 (112x64B)
#define STAGES   5
#define SMEM_DYN (STAGES * STG + 128)

// ====================== device scratch ======================
__device__ __align__(16) __half g_x[(size_t)32 * 58 * 58 * 256];  // padded NHWC fp16
__device__ __align__(16) __half g_w[(size_t)9 * 256 * 256];       // [tap][co][ci] = +-1

// ====================== helpers ======================
__device__ __forceinline__ uint32_t smem_u32(const void* p) {
    uint32_t a;
    asm("{ .reg .u64 t; cvta.to.shared.u64 t, %1; cvt.u32.u64 %0, t; }" : "=r"(a) : "l"(p));
    return a;
}
__device__ __forceinline__ void cp16(uint32_t d, const void* s) {
    asm volatile("cp.async.cg.shared.global [%0], [%1], 16;" :: "r"(d), "l"(s) : "memory");
}
__device__ __forceinline__ void ldsm_x4(uint32_t* r, uint32_t a) {
    asm volatile("ldmatrix.sync.aligned.m8n8.x4.shared.b16 {%0,%1,%2,%3}, [%4];"
                 : "=r"(r[0]), "=r"(r[1]), "=r"(r[2]), "=r"(r[3]) : "r"(a));
}
__device__ __forceinline__ void ldsm_x2(uint32_t* r, uint32_t a) {
    asm volatile("ldmatrix.sync.aligned.m8n8.x2.shared.b16 {%0,%1}, [%2];"
                 : "=r"(r[0]), "=r"(r[1]) : "r"(a));
}
__device__ __forceinline__ void mma16816(float* c, uint32_t a0, uint32_t a1, uint32_t a2,
                                         uint32_t a3, uint32_t b0, uint32_t b1) {
    asm volatile(
        "mma.sync.aligned.m16n8k16.row.col.f32.f16.f16.f32 "
        "{%0,%1,%2,%3}, {%4,%5,%6,%7}, {%8,%9}, {%0,%1,%2,%3};"
        : "+f"(c[0]), "+f"(c[1]), "+f"(c[2]), "+f"(c[3])
        : "r"(a0), "r"(a1), "r"(a2), "r"(a3), "r"(b0), "r"(b1));
}

// ====================== prep kernels ======================
__global__ void zero_border_kernel() {
    const int n = blockIdx.x;                       // 32 images
    __half* xb = g_x + (size_t)n * 861184;
    for (int c = threadIdx.x; c < 7296; c += 256) { // 228 border px * 32 uint4
        int px = c >> 5, q = c & 31;
        int h, w;
        if (px < 58)       { h = 0;        w = px; }
        else if (px < 116) { h = 57;       w = px - 58; }
        else if (px < 172) { h = px - 115; w = 0; }
        else               { h = px - 171; w = 57; }
        reinterpret_cast<uint4*>(xb + ((size_t)h * 58 + w) * 256)[q] =
            make_uint4(0u, 0u, 0u, 0u);
    }
}

// x NCHW f32 -> g_x padded NHWC fp16 (linear ci). grid 32*56*2, 256 thr.
__global__ void prep_x_kernel(const float* __restrict__ x) {
    __shared__ float tile[128][57];
    const int b  = blockIdx.x;
    const int ch = b & 1;
    const int h  = (b >> 1) % 56;
    const int n  = (b >> 1) / 56;
    const float* src = x + (size_t)(n * 256 + ch * 128) * 3136 + h * 56;
    for (int i = threadIdx.x; i < 128 * 56; i += 256) {
        int ci = i / 56, w = i - 56 * ci;
        tile[ci][w] = src[(size_t)ci * 3136 + w];
    }
    __syncthreads();
    __half* dst = g_x + (size_t)n * 861184 + ((h + 1) * 58 + 1) * 256;
    for (int j = threadIdx.x; j < 64 * 56; j += 256) {
        int w  = j >> 6, cp = j & 63;
        int ci = ch * 128 + 2 * cp;
        __half2 v = __floats2half2_rn(tile[2 * cp][w], tile[2 * cp + 1][w]);
        *reinterpret_cast<__half2*>(dst + (size_t)w * 256 + ci) = v;
    }
}

// weight [co][ci][3][3] f32 -> g_w[tap][co][ci] = +-1 fp16. grid 2304, 256 thr.
__global__ void prep_w_kernel(const float* __restrict__ w) {
    int idx = blockIdx.x * 256 + threadIdx.x;             // co*2304 + ci*9 + tap
    int co  = idx / 2304;
    int r   = idx - co * 2304;
    int ci  = r / 9;
    int tap = r - ci * 9;
    g_w[(size_t)(tap * 256 + co) * 256 + ci] = __float2half(w[idx] >= 0.f ? 1.f : -1.f);
}

// ====================== main kernel ======================
// grid 1792 = 2 cout-halves * 28 row-pairs * 32 images; 128 threads (4 warps 2x2).
// Warp tile 64x56: 4 m16-frags x 7 n8-frags, 2 ksteps per 32-ci stage.
// Smem swizzle: 64B rows, 16B bank index = chunk ^ ((row>>1)&3)  (ldmatrix conflict-free)
__global__ void __launch_bounds__(128, 3)
bconv_main_kernel(const float* __restrict__ bias, float* __restrict__ out) {
    extern __shared__ char dsm[];
    const uint32_t base = (smem_u32(dsm) + 127u) & ~127u;

    const int tid  = threadIdx.x;
    const int lane = tid & 31;
    const int wid  = tid >> 5;
    const int g    = lane >> 2;
    const int t    = lane & 3;
    const int wm   = wid >> 1;     // 0..1  (m warp half)
    const int wn   = wid & 1;      // 0..1  (output row within pair)

    const int bid = blockIdx.x;
    const int mb  = bid & 1;
    const int rp  = (bid >> 1) % 28;
    const int n   = bid / 56;
    const int h0  = rp * 2;

    const __half* xn = g_x + (size_t)n * 861184;

    // ---- per-thread cp.async chunk tables (16B chunks) ----
    uint32_t aD[4], aG[4], bD[4], bG[4];
#pragma unroll
    for (int i = 0; i < 4; i++) {
        int c   = tid + 128 * i;          // A chunk 0..511
        int row = c >> 2, cb = c & 3;
        aD[i] = (uint32_t)(row * 64 + ((cb ^ ((row >> 1) & 3)) << 4));
        aG[i] = (uint32_t)((mb * 128 + row) * 256 + cb * 8);
    }
#pragma unroll
    for (int i = 0; i < 4; i++) {
        int c    = (i < 3) ? (tid + 128 * i) : (384 + tid);   // B chunk 0..447 (i==3: tid<64)
        int prow = c >> 2, cb = c & 3;
        int pr   = prow / 56, pw = prow - 56 * pr;
        bD[i] = (uint32_t)(8192 + prow * 64 + ((cb ^ ((prow >> 1) & 3)) << 4));
        bG[i] = (uint32_t)(((h0 + pr) * 58 + pw) * 256 + cb * 8);
    }

    auto load_stage = [&](int s, uint32_t sb) {
        int tap = s >> 3, kc = s & 7;
        int dh  = tap / 3, dw = tap - 3 * dh;
        uint32_t ad = (uint32_t)(tap * 65536 + kc * 32);
        uint32_t bd = (uint32_t)((dh * 58 + dw) * 256 + kc * 32);
        cp16(sb + aD[0], g_w + aG[0] + ad);
        cp16(sb + aD[1], g_w + aG[1] + ad);
        cp16(sb + aD[2], g_w + aG[2] + ad);
        cp16(sb + aD[3], g_w + aG[3] + ad);
        cp16(sb + bD[0], xn + bG[0] + bd);
        cp16(sb + bD[1], xn + bG[1] + bd);
        cp16(sb + bD[2], xn + bG[2] + bd);
        if (tid < 64) cp16(sb + bD[3], xn + bG[3] + bd);
        asm volatile("cp.async.commit_group;" ::: "memory");
    };

    // ---- ldmatrix lane addresses (kstep 0; kstep 1 = XOR 0x20) ----
    // A x4 (per mi): m0 = rows 0-7 klo -> a0, m1 = rows 8-15 klo -> a1,
    //                m2 = rows 0-7 khi -> a2, m3 = rows 8-15 khi -> a3
    uint32_t rA[4];
    {
        int rl   = (lane & 7) + ((lane >> 3) & 1) * 8;
        int half = lane >> 4;
#pragma unroll
        for (int mi = 0; mi < 4; mi++) {
            int row = wm * 64 + mi * 16 + rl;
            rA[mi] = (uint32_t)(row * 64 + ((half ^ ((row >> 1) & 3)) << 4));
        }
    }
    // B x4 NO-TRANS (per pair pi): m0 = pix 0-7 klo -> b0, m1 = pix 0-7 khi -> b1,
    //                              m2 = pix 8-15 klo, m3 = pix 8-15 khi
    uint32_t rB[4];
    {
        int pl   = (lane & 7) + (lane >> 4) * 8;
        int half = (lane >> 3) & 1;
#pragma unroll
        for (int pi = 0; pi < 3; pi++) {
            int pix = wn * 56 + pi * 16 + pl;
            rB[pi] = (uint32_t)(8192 + pix * 64 + ((half ^ ((pix >> 1) & 3)) << 4));
        }
        // x2 for ni=6 (lanes 0-15 active: pix 48-55, klo/khi)
        int pix6 = wn * 56 + 48 + (lane & 7);
        rB[3] = (uint32_t)(8192 + pix6 * 64 + ((half ^ ((pix6 >> 1) & 3)) << 4));
    }

    float acc[4][7][4];
#pragma unroll
    for (int mi = 0; mi < 4; mi++)
#pragma unroll
        for (int ni = 0; ni < 7; ni++)
#pragma unroll
            for (int k = 0; k < 4; k++) acc[mi][ni][k] = 0.f;

    // ---- prologue: stages 0..3 ----
    for (int s = 0; s < 4; s++) load_stage(s, base + s * STG);
    asm volatile("cp.async.wait_group 3;" ::: "memory");
    __syncthreads();

    // ---- mainloop: 72 stages, 5 buffers ----
    int cbuf = 0, lbuf = 4;
    for (int s = 0; s < 72; s++) {
        if (s + 4 < 72) load_stage(s + 4, base + lbuf * STG);
        else asm volatile("cp.async.commit_group;" ::: "memory");
        lbuf = (lbuf == 4) ? 0 : lbuf + 1;

        const uint32_t sb = base + cbuf * STG;
        cbuf = (cbuf == 4) ? 0 : cbuf + 1;
#pragma unroll
        for (int ks = 0; ks < 2; ks++) {
            const uint32_t xr = (uint32_t)(ks << 5);
            uint32_t a[4][4];
#pragma unroll
            for (int mi = 0; mi < 4; mi++) ldsm_x4(a[mi], sb + (rA[mi] ^ xr));
#pragma unroll
            for (int pi = 0; pi < 3; pi++) {
                uint32_t b[4];
                ldsm_x4(b, sb + (rB[pi] ^ xr));
#pragma unroll
                for (int mi = 0; mi < 4; mi++) {
                    mma16816(acc[mi][2 * pi],     a[mi][0], a[mi][1], a[mi][2], a[mi][3], b[0], b[1]);
                    mma16816(acc[mi][2 * pi + 1], a[mi][0], a[mi][1], a[mi][2], a[mi][3], b[2], b[3]);
                }
            }
            uint32_t b6[2];
            ldsm_x2(b6, sb + (rB[3] ^ xr));
#pragma unroll
            for (int mi = 0; mi < 4; mi++)
                mma16816(acc[mi][6], a[mi][0], a[mi][1], a[mi][2], a[mi][3], b6[0], b6[1]);
        }
        asm volatile("cp.async.wait_group 3;" ::: "memory");
        __syncthreads();
    }

    // ---- epilogue: registers -> gmem (float2), + binarized bias ----
    const int h = h0 + wn;
#pragma unroll
    for (int mi = 0; mi < 4; mi++) {
        int mlo = mb * 128 + wm * 64 + mi * 16 + g;
        float blo = (bias[mlo]     >= 0.f) ? 1.f : -1.f;
        float bhi = (bias[mlo + 8] >= 0.f) ? 1.f : -1.f;
        size_t olo = ((size_t)(n * 256 + mlo)) * 3136 + h * 56;
        size_t ohi = olo + (size_t)8 * 3136;
#pragma unroll
        for (int ni = 0; ni < 7; ni++) {
            int w = ni * 8 + 2 * t;
            float2 v0 = make_float2(acc[mi][ni][0] + blo, acc[mi][ni][1] + blo);
            float2 v1 = make_float2(acc[mi][ni][2] + bhi, acc[mi][ni][3] + bhi);
            *reinterpret_cast<float2*>(out + olo + w) = v0;
            *reinterpret_cast<float2*>(out + ohi + w) = v1;
        }
    }
}

// ====================== launch ======================
extern "C" void kernel_launch(void* const* d_in, const int* in_sizes, int n_in,
                              void* d_out, int out_size) {
    const float* x    = (const float*)d_in[0];
    const float* w    = (const float*)d_in[1];
    const float* bias = (const float*)d_in[2];
    float* out        = (float*)d_out;

    cudaFuncSetAttribute(bconv_main_kernel,
                         cudaFuncAttributeMaxDynamicSharedMemorySize, SMEM_DYN);

    zero_border_kernel<<<32, 256>>>();
    prep_x_kernel<<<32 * 56 * 2, 256>>>(x);
    prep_w_kernel<<<2304, 256>>>(w);
    bconv_main_kernel<<<1792, 128, SMEM_DYN>>>(bias, out);
}

// round 9
// speedup vs baseline: 1.3591x; 1.1432x over previous
#include <cuda_runtime.h>
#include <cuda_fp16.h>
#include <cstdint>

// ====================== tile/pipeline constants ======================
// CTA: 128 threads (4 warps 2x2), tile 128 couts x 112 pixels (2 output rows)
#define STG      15360            // per-stage smem: A 8192 (128x64B) + B 7168 (112x64B)
#define STAGES   4
#define SMEM_DYN (STAGES * STG + 128)

// ====================== device scratch ======================
__device__ __align__(16) __half g_x[(size_t)32 * 58 * 58 * 256];  // padded NHWC fp16
__device__ __align__(16) __half g_w[(size_t)9 * 256 * 256];       // [tap][co][ci] = +-1

// ====================== helpers ======================
__device__ __forceinline__ uint32_t smem_u32(const void* p) {
    uint32_t a;
    asm("{ .reg .u64 t; cvta.to.shared.u64 t, %1; cvt.u32.u64 %0, t; }" : "=r"(a) : "l"(p));
    return a;
}
__device__ __forceinline__ void cp16(uint32_t d, const void* s) {
    asm volatile("cp.async.cg.shared.global [%0], [%1], 16;" :: "r"(d), "l"(s) : "memory");
}
__device__ __forceinline__ void ldsm_x4(uint32_t* r, uint32_t a) {
    asm volatile("ldmatrix.sync.aligned.m8n8.x4.shared.b16 {%0,%1,%2,%3}, [%4];"
                 : "=r"(r[0]), "=r"(r[1]), "=r"(r[2]), "=r"(r[3]) : "r"(a));
}
__device__ __forceinline__ void ldsm_x2(uint32_t* r, uint32_t a) {
    asm volatile("ldmatrix.sync.aligned.m8n8.x2.shared.b16 {%0,%1}, [%2];"
                 : "=r"(r[0]), "=r"(r[1]) : "r"(a));
}
__device__ __forceinline__ void mma16816(float* c, uint32_t a0, uint32_t a1, uint32_t a2,
                                         uint32_t a3, uint32_t b0, uint32_t b1) {
    asm volatile(
        "mma.sync.aligned.m16n8k16.row.col.f32.f16.f16.f32 "
        "{%0,%1,%2,%3}, {%4,%5,%6,%7}, {%8,%9}, {%0,%1,%2,%3};"
        : "+f"(c[0]), "+f"(c[1]), "+f"(c[2]), "+f"(c[3])
        : "r"(a0), "r"(a1), "r"(a2), "r"(a3), "r"(b0), "r"(b1));
}

// ====================== prep kernels ======================
__global__ void zero_border_kernel() {
    const int n = blockIdx.x;                       // 32 images
    __half* xb = g_x + (size_t)n * 861184;
    for (int c = threadIdx.x; c < 7296; c += 256) { // 228 border px * 32 uint4
        int px = c >> 5, q = c & 31;
        int h, w;
        if (px < 58)       { h = 0;        w = px; }
        else if (px < 116) { h = 57;       w = px - 58; }
        else if (px < 172) { h = px - 115; w = 0; }
        else               { h = px - 171; w = 57; }
        reinterpret_cast<uint4*>(xb + ((size_t)h * 58 + w) * 256)[q] =
            make_uint4(0u, 0u, 0u, 0u);
    }
}

// x NCHW f32 -> g_x padded NHWC fp16 (linear ci). grid 32*56*2, 256 thr.
__global__ void prep_x_kernel(const float* __restrict__ x) {
    __shared__ float tile[128][57];
    const int b  = blockIdx.x;
    const int ch = b & 1;
    const int h  = (b >> 1) % 56;
    const int n  = (b >> 1) / 56;
    const float* src = x + (size_t)(n * 256 + ch * 128) * 3136 + h * 56;
    for (int i = threadIdx.x; i < 128 * 56; i += 256) {
        int ci = i / 56, w = i - 56 * ci;
        tile[ci][w] = src[(size_t)ci * 3136 + w];
    }
    __syncthreads();
    __half* dst = g_x + (size_t)n * 861184 + ((h + 1) * 58 + 1) * 256;
    for (int j = threadIdx.x; j < 64 * 56; j += 256) {
        int w  = j >> 6, cp = j & 63;
        int ci = ch * 128 + 2 * cp;
        __half2 v = __floats2half2_rn(tile[2 * cp][w], tile[2 * cp + 1][w]);
        *reinterpret_cast<__half2*>(dst + (size_t)w * 256 + ci) = v;
    }
}

// weight [co][ci][3][3] f32 -> g_w[tap][co][ci] = +-1 fp16. grid 2304, 256 thr.
__global__ void prep_w_kernel(const float* __restrict__ w) {
    int idx = blockIdx.x * 256 + threadIdx.x;             // co*2304 + ci*9 + tap
    int co  = idx / 2304;
    int r   = idx - co * 2304;
    int ci  = r / 9;
    int tap = r - ci * 9;
    g_w[(size_t)(tap * 256 + co) * 256 + ci] = __float2half(w[idx] >= 0.f ? 1.f : -1.f);
}

// ====================== main kernel ======================
// grid 1792 = 2 cout-halves * 28 row-pairs * 32 images; 128 threads (4 warps 2x2).
// Warp tile 64x56: 4 m16-frags x 7 n8-frags, 2 ksteps per 32-ci stage.
// Smem swizzle: 64B rows, 16B bank index = chunk ^ ((row>>1)&3)  (ldmatrix conflict-free)
__global__ void __launch_bounds__(128, 3)
bconv_main_kernel(const float* __restrict__ bias, float* __restrict__ out) {
    extern __shared__ char dsm[];
    const uint32_t base = (smem_u32(dsm) + 127u) & ~127u;

    const int tid  = threadIdx.x;
    const int lane = tid & 31;
    const int wid  = tid >> 5;
    const int g    = lane >> 2;
    const int t    = lane & 3;
    const int wm   = wid >> 1;     // 0..1  (m warp half)
    const int wn   = wid & 1;      // 0..1  (output row within pair)

    const int bid = blockIdx.x;
    const int mb  = bid & 1;
    const int rp  = (bid >> 1) % 28;
    const int n   = bid / 56;
    const int h0  = rp * 2;

    const __half* xn = g_x + (size_t)n * 861184;

    // ---- per-thread cp.async chunk tables (16B chunks) ----
    uint32_t aD[4], aG[4], bD[4], bG[4];
#pragma unroll
    for (int i = 0; i < 4; i++) {
        int c   = tid + 128 * i;          // A chunk 0..511
        int row = c >> 2, cb = c & 3;
        aD[i] = (uint32_t)(row * 64 + ((cb ^ ((row >> 1) & 3)) << 4));
        aG[i] = (uint32_t)((mb * 128 + row) * 256 + cb * 8);
    }
#pragma unroll
    for (int i = 0; i < 4; i++) {
        int c    = (i < 3) ? (tid + 128 * i) : (384 + tid);   // B chunk 0..447 (i==3: tid<64)
        int prow = c >> 2, cb = c & 3;
        int pr   = prow / 56, pw = prow - 56 * pr;
        bD[i] = (uint32_t)(8192 + prow * 64 + ((cb ^ ((prow >> 1) & 3)) << 4));
        bG[i] = (uint32_t)(((h0 + pr) * 58 + pw) * 256 + cb * 8);
    }

    auto load_stage = [&](int s, uint32_t sb) {
        int tap = s >> 3, kc = s & 7;
        int dh  = tap / 3, dw = tap - 3 * dh;
        uint32_t ad = (uint32_t)(tap * 65536 + kc * 32);
        uint32_t bd = (uint32_t)((dh * 58 + dw) * 256 + kc * 32);
        cp16(sb + aD[0], g_w + aG[0] + ad);
        cp16(sb + aD[1], g_w + aG[1] + ad);
        cp16(sb + aD[2], g_w + aG[2] + ad);
        cp16(sb + aD[3], g_w + aG[3] + ad);
        cp16(sb + bD[0], xn + bG[0] + bd);
        cp16(sb + bD[1], xn + bG[1] + bd);
        cp16(sb + bD[2], xn + bG[2] + bd);
        if (tid < 64) cp16(sb + bD[3], xn + bG[3] + bd);
        asm volatile("cp.async.commit_group;" ::: "memory");
    };

    // ---- ldmatrix lane addresses (kstep 0; kstep 1 = XOR 0x20) ----
    // A x4 (per mi): m0 = rows 0-7 klo -> a0, m1 = rows 8-15 klo -> a1,
    //                m2 = rows 0-7 khi -> a2, m3 = rows 8-15 khi -> a3
    uint32_t rA[4];
    {
        int rl   = (lane & 7) + ((lane >> 3) & 1) * 8;
        int half = lane >> 4;
#pragma unroll
        for (int mi = 0; mi < 4; mi++) {
            int row = wm * 64 + mi * 16 + rl;
            rA[mi] = (uint32_t)(row * 64 + ((half ^ ((row >> 1) & 3)) << 4));
        }
    }
    // B x4 NO-TRANS (per pair pi): m0 = pix 0-7 klo -> b0, m1 = pix 0-7 khi -> b1,
    //                              m2 = pix 8-15 klo, m3 = pix 8-15 khi
    uint32_t rB[4];
    {
        int pl   = (lane & 7) + (lane >> 4) * 8;
        int half = (lane >> 3) & 1;
#pragma unroll
        for (int pi = 0; pi < 3; pi++) {
            int pix = wn * 56 + pi * 16 + pl;
            rB[pi] = (uint32_t)(8192 + pix * 64 + ((half ^ ((pix >> 1) & 3)) << 4));
        }
        // x2 for ni=6 (lanes 0-15 active: pix 48-55, klo/khi)
        int pix6 = wn * 56 + 48 + (lane & 7);
        rB[3] = (uint32_t)(8192 + pix6 * 64 + ((half ^ ((pix6 >> 1) & 3)) << 4));
    }

    float acc[4][7][4];
#pragma unroll
    for (int mi = 0; mi < 4; mi++)
#pragma unroll
        for (int ni = 0; ni < 7; ni++)
#pragma unroll
            for (int k = 0; k < 4; k++) acc[mi][ni][k] = 0.f;

    // ---- prologue: stages 0..2 ----
    for (int s = 0; s < 3; s++) load_stage(s, base + s * STG);
    asm volatile("cp.async.wait_group 2;" ::: "memory");
    __syncthreads();

    // ---- mainloop: 72 stages, 4 buffers ----
    for (int s = 0; s < 72; s++) {
        if (s + 3 < 72) load_stage(s + 3, base + ((s + 3) & 3) * STG);
        else asm volatile("cp.async.commit_group;" ::: "memory");

        const uint32_t sb = base + (s & 3) * STG;
#pragma unroll
        for (int ks = 0; ks < 2; ks++) {
            const uint32_t xr = (uint32_t)(ks << 5);
            uint32_t a[4][4];
#pragma unroll
            for (int mi = 0; mi < 4; mi++) ldsm_x4(a[mi], sb + (rA[mi] ^ xr));
#pragma unroll
            for (int pi = 0; pi < 3; pi++) {
                uint32_t b[4];
                ldsm_x4(b, sb + (rB[pi] ^ xr));
#pragma unroll
                for (int mi = 0; mi < 4; mi++) {
                    mma16816(acc[mi][2 * pi],     a[mi][0], a[mi][1], a[mi][2], a[mi][3], b[0], b[1]);
                    mma16816(acc[mi][2 * pi + 1], a[mi][0], a[mi][1], a[mi][2], a[mi][3], b[2], b[3]);
                }
            }
            uint32_t b6[2];
            ldsm_x2(b6, sb + (rB[3] ^ xr));
#pragma unroll
            for (int mi = 0; mi < 4; mi++)
                mma16816(acc[mi][6], a[mi][0], a[mi][1], a[mi][2], a[mi][3], b6[0], b6[1]);
        }
        asm volatile("cp.async.wait_group 2;" ::: "memory");
        __syncthreads();
    }

    // ---- epilogue: registers -> gmem (float2), + binarized bias ----
    const int h = h0 + wn;
#pragma unroll
    for (int mi = 0; mi < 4; mi++) {
        int mlo = mb * 128 + wm * 64 + mi * 16 + g;
        float blo = (bias[mlo]     >= 0.f) ? 1.f : -1.f;
        float bhi = (bias[mlo + 8] >= 0.f) ? 1.f : -1.f;
        size_t olo = ((size_t)(n * 256 + mlo)) * 3136 + h * 56;
        size_t ohi = olo + (size_t)8 * 3136;
#pragma unroll
        for (int ni = 0; ni < 7; ni++) {
            int w = ni * 8 + 2 * t;
            float2 v0 = make_float2(acc[mi][ni][0] + blo, acc[mi][ni][1] + blo);
            float2 v1 = make_float2(acc[mi][ni][2] + bhi, acc[mi][ni][3] + bhi);
            *reinterpret_cast<float2*>(out + olo + w) = v0;
            *reinterpret_cast<float2*>(out + ohi + w) = v1;
        }
    }
}

// ====================== launch ======================
extern "C" void kernel_launch(void* const* d_in, const int* in_sizes, int n_in,
                              void* d_out, int out_size) {
    const float* x    = (const float*)d_in[0];
    const float* w    = (const float*)d_in[1];
    const float* bias = (const float*)d_in[2];
    float* out        = (float*)d_out;

    cudaFuncSetAttribute(bconv_main_kernel,
                         cudaFuncAttributeMaxDynamicSharedMemorySize, SMEM_DYN);

    zero_border_kernel<<<32, 256>>>();
    prep_x_kernel<<<32 * 56 * 2, 256>>>(x);
    prep_w_kernel<<<2304, 256>>>(w);
    bconv_main_kernel<<<1792, 128, SMEM_DYN>>>(bias, out);
}